// round 9
// baseline (speedup 1.0000x reference)
#include <cuda_runtime.h>
#include <cstdint>
#include <math.h>

#define NN 128
#define MM 64
#define NB 4                     // batches per CTA
#define NSTAGE 2
#define TILE_B (NN * MM * 4)     // 32768 bytes per batch tile
#define KEY_B  (MM * 4)          // 256 bytes
#define STAGE_B (TILE_B + KEY_B) // 33024, 16B-aligned
#define SMEM_BYTES (NSTAGE * STAGE_B + NN * 4 + 64)

__device__ __forceinline__ float softplus_f(float x) {
    return x > 0.f ? x + log1pf(expf(-x)) : log1pf(expf(x));
}

__device__ __forceinline__ float warp_sum(float v) {
    #pragma unroll
    for (int o = 16; o > 0; o >>= 1) v += __shfl_xor_sync(0xffffffffu, v, o);
    return v;
}

__device__ __forceinline__ unsigned smem_u32(const void* p) {
    return (unsigned)__cvta_generic_to_shared(p);
}

#define CP_ASYNC16(dst, src) \
    asm volatile("cp.async.cg.shared.global [%0], [%1], 16;" \
                 :: "r"(dst), "l"(src) : "memory")
#define CP_COMMIT() asm volatile("cp.async.commit_group;" ::: "memory")
#define CP_WAIT1()  asm volatile("cp.async.wait_group 1;" ::: "memory")

__global__ __launch_bounds__(128) void rom_kernel(
    const float* __restrict__ memory,   // [B, N, M]
    const float* __restrict__ key,      // [B, M]
    const float* __restrict__ beta_in,  // [B, 1]
    const float* __restrict__ g_in,     // [B, 1]
    const float* __restrict__ s_in,     // [B, 3]
    const float* __restrict__ gamma_in, // [B, 1]
    const float* __restrict__ w_prev,   // [B, N]
    float* __restrict__ out)            // [B, N]
{
    extern __shared__ char smem[];
    float* shw  = (float*)(smem + NSTAGE * STAGE_B);
    float* redA = shw + NN;
    float* redB = redA + 4;

    const int b0   = blockIdx.x * NB;
    const int tid  = threadIdx.x;
    const int lane = tid & 31;
    const int wid  = tid >> 5;
    const unsigned sbase = smem_u32(smem);

    // ---- Producer: issue stage s (tile + key) for batch bb ----
    auto issue_stage = [&](int s, int bb) {
        const unsigned tb = sbase + s * STAGE_B;
        const char* gsrc = (const char*)memory + (size_t)bb * TILE_B;
        #pragma unroll
        for (int it = 0; it < 16; ++it) {
            const int q   = it * 128 + tid;      // 16B chunk index in tile
            const int row = q >> 4;
            const int c   = q & 15;
            const unsigned dst = tb + row * 256 + ((c ^ (row & 7)) << 4);
            CP_ASYNC16(dst, gsrc + q * 16);
        }
        if (tid < 16) {
            CP_ASYNC16(tb + TILE_B + tid * 16,
                       (const char*)key + (size_t)bb * KEY_B + tid * 16);
        }
    };

    // ---- Prologue: fill both stages ----
    issue_stage(0, b0);     CP_COMMIT();
    issue_stage(1, b0 + 1); CP_COMMIT();

    #pragma unroll
    for (int j = 0; j < NB; ++j) {
        const int s  = j & 1;
        const int bb = b0 + j;

        // Prefetch scalars + w_prev (independent of cp.async stages)
        const float braw = __ldg(beta_in + bb);
        const float graw = __ldg(g_in + bb);
        const float s0r  = __ldg(s_in + bb * 3 + 0);
        const float s1r  = __ldg(s_in + bb * 3 + 1);
        const float s2r  = __ldg(s_in + bb * 3 + 2);
        const float gmr  = __ldg(gamma_in + bb);
        const float wpv  = __ldg(w_prev + (size_t)bb * NN + tid);

        CP_WAIT1();              // stage j complete (<=1 group pending)
        __syncthreads();         // visibility across threads

        // ---- Consume: thread tid owns row tid; swizzled LDS is
        //      conflict-free (structural 4-phase minimum per LDS.128) ----
        const float4* tile = (const float4*)(smem + s * STAGE_B);
        const float4* kk4  = (const float4*)(smem + s * STAGE_B + TILE_B);
        float dot = 0.f, nrm = 0.f, kn = 0.f;
        const int rbase = tid << 4;
        const int rsw   = tid & 7;
        #pragma unroll
        for (int c = 0; c < 16; ++c) {
            float4 k4 = kk4[c];                     // broadcast
            float4 v  = tile[rbase + (c ^ rsw)];
            dot += v.x * k4.x + v.y * k4.y + v.z * k4.z + v.w * k4.w;
            nrm += v.x * v.x  + v.y * v.y  + v.z * v.z  + v.w * v.w;
            kn  += k4.x * k4.x + k4.y * k4.y + k4.z * k4.z + k4.w * k4.w;
        }
        __syncthreads();         // everyone done reading stage s

        // ---- Refill the freed buffer immediately (overlaps epilogue) ----
        if (j + NSTAGE < NB) issue_stage(s, bb + NSTAGE);
        CP_COMMIT();             // commit (possibly empty) to keep group math

        // ---- Epilogue (runs with next stages' loads in flight) ----
        const float beta  = softplus_f(braw);
        const float gg    = 1.f / (1.f + __expf(-graw));
        const float smax  = fmaxf(s0r, fmaxf(s1r, s2r));
        const float e0 = __expf(s0r - smax), e1 = __expf(s1r - smax),
                    e2 = __expf(s2r - smax);
        const float sinv = 1.f / (e0 + e1 + e2);
        const float t0 = e0 * sinv, t1 = e1 * sinv, t2 = e2 * sinv;
        const float gamma = 1.f + softplus_f(gmr);

        const float mem_norm = fmaxf(sqrtf(nrm), 1e-8f);
        const float key_norm = fmaxf(sqrtf(kn), 1e-8f);
        const float z = beta * (dot / (mem_norm * key_norm));

        // softmax without max-subtraction: |z| <= beta (cos in [-1,1]), safe
        const float e = __expf(z);
        float se = warp_sum(e);
        if (lane == 0) redB[wid] = se;
        __syncthreads();
        const float tot = redB[0] + redB[1] + redB[2] + redB[3];
        const float wc = e / tot;

        const float wg = gg * wc + (1.f - gg) * wpv;
        shw[tid] = wg;
        __syncthreads();

        const float wh = shw[(tid + NN - 1) & (NN - 1)] * t0
                       + wg * t1
                       + shw[(tid + 1) & (NN - 1)] * t2;

        const float w = __powf(wh, gamma);
        float sw2 = warp_sum(w);
        if (lane == 0) redA[wid] = sw2;
        __syncthreads();
        const float tw = redA[0] + redA[1] + redA[2] + redA[3] + 1e-16f;

        out[(size_t)bb * NN + tid] = w / tw;
    }
}

extern "C" void kernel_launch(void* const* d_in, const int* in_sizes, int n_in,
                              void* d_out, int out_size) {
    const float* memory  = (const float*)d_in[0];  // [B, N, M]
    const float* k       = (const float*)d_in[1];  // [B, M]
    const float* beta    = (const float*)d_in[2];  // [B, 1]
    const float* g       = (const float*)d_in[3];  // [B, 1]
    const float* s       = (const float*)d_in[4];  // [B, 3]
    const float* gamma   = (const float*)d_in[5];  // [B, 1]
    const float* w_prev  = (const float*)d_in[6];  // [B, N]
    float* out = (float*)d_out;

    static bool attr_set = false;
    if (!attr_set) {
        cudaFuncSetAttribute(rom_kernel,
                             cudaFuncAttributeMaxDynamicSharedMemorySize,
                             SMEM_BYTES);
        attr_set = true;
    }

    int B = in_sizes[0] / (NN * MM);
    rom_kernel<<<B / NB, 128, SMEM_BYTES>>>(memory, k, beta, g, s, gamma,
                                            w_prev, out);
}

// round 10
// speedup vs baseline: 1.1744x; 1.1744x over previous
#include <cuda_runtime.h>
#include <cstdint>
#include <math.h>

#define NN 128
#define MM 64
#define NB 4                       // batches per CTA
#define HALF_B 16384               // half tile: 64 rows * 256 B
#define STAGE_T (HALF_B + 256)     // + key slot (only used by h0 stages)
#define NSTAGE 3
#define SMEM_BYTES (NSTAGE * STAGE_T + NN * 4 + 64)

__device__ __forceinline__ float softplus_f(float x) {
    return x > 0.f ? x + log1pf(expf(-x)) : log1pf(expf(x));
}

__device__ __forceinline__ float warp_sum(float v) {
    #pragma unroll
    for (int o = 16; o > 0; o >>= 1) v += __shfl_xor_sync(0xffffffffu, v, o);
    return v;
}

__device__ __forceinline__ unsigned smem_u32(const void* p) {
    return (unsigned)__cvta_generic_to_shared(p);
}

#define CP_ASYNC16(dst, src) \
    asm volatile("cp.async.cg.shared.global [%0], [%1], 16;" \
                 :: "r"(dst), "l"(src) : "memory")
#define CP_COMMIT() asm volatile("cp.async.commit_group;" ::: "memory")
#define CP_WAIT1()  asm volatile("cp.async.wait_group 1;" ::: "memory")
#define CP_WAIT0()  asm volatile("cp.async.wait_group 0;" ::: "memory")

__global__ __launch_bounds__(128) void rom_kernel(
    const float* __restrict__ memory,   // [B, N, M]
    const float* __restrict__ key,      // [B, M]
    const float* __restrict__ beta_in,  // [B, 1]
    const float* __restrict__ g_in,     // [B, 1]
    const float* __restrict__ s_in,     // [B, 3]
    const float* __restrict__ gamma_in, // [B, 1]
    const float* __restrict__ w_prev,   // [B, N]
    float* __restrict__ out)            // [B, N]
{
    extern __shared__ char smem[];
    float* shw  = (float*)(smem + NSTAGE * STAGE_T);
    float* redA = shw + NN;
    float* redB = redA + 4;

    const int b0   = blockIdx.x * NB;
    const int tid  = threadIdx.x;
    const int lane = tid & 31;
    const int wid  = tid >> 5;
    const unsigned sbase = smem_u32(smem);

    // ---- Producer: one HALF tile (64 rows) of batch bb into stage st.
    //      Chunk c of row rp stored at slot (c ^ (rp&7)) — consume-side
    //      reads are then conflict-free per 8-lane subgroup. ----
    auto issue_half = [&](int st, int bb, int h) {
        const unsigned dstb = sbase + st * STAGE_T;
        const char* gsrc = (const char*)memory + (size_t)bb * 32768 + h * HALF_B;
        #pragma unroll
        for (int it = 0; it < 8; ++it) {
            const int q  = it * 128 + tid;       // 16B-chunk index in half
            const int rp = q >> 4;
            const int c  = q & 15;
            const unsigned dst = dstb + rp * 256 + ((c ^ (rp & 7)) << 4);
            CP_ASYNC16(dst, gsrc + q * 16);
        }
        if (h == 0 && tid < 16) {
            CP_ASYNC16(dstb + HALF_B + tid * 16,
                       (const char*)key + (size_t)bb * 256 + tid * 16);
        }
        CP_COMMIT();
    };

    // ---- Prologue: 3 halves in flight (b0h0, b0h1, b1h0) ----
    issue_half(0, b0, 0);
    issue_half(1, b0, 1);
    if (NB > 1) issue_half(2, b0 + 1, 0);

    const int h   = tid >> 6;           // which half holds my row
    const int rp  = tid & 63;           // row within half
    const int rsw = rp & 7;

    #pragma unroll
    for (int j = 0; j < NB; ++j) {
        const int bb  = b0 + j;
        const int st0 = (2 * j) % 3;            // stage of h0 (has key)
        const int st1 = (2 * j + 1) % 3;        // stage of h1

        // Prefetch scalars + w_prev (independent traffic)
        const float braw = __ldg(beta_in + bb);
        const float graw = __ldg(g_in + bb);
        const float s0r  = __ldg(s_in + bb * 3 + 0);
        const float s1r  = __ldg(s_in + bb * 3 + 1);
        const float s2r  = __ldg(s_in + bb * 3 + 2);
        const float gmr  = __ldg(gamma_in + bb);
        const float wpv  = __ldg(w_prev + (size_t)bb * NN + tid);

        if (j < NB - 1) { CP_WAIT1(); } else { CP_WAIT0(); }
        __syncthreads();

        // ---- Consume: thread tid owns row tid. tile[i^rsw] = chunk i;
        //      k4[i] is a warp-broadcast. Conflict-free per subgroup. ----
        const int stA = (h == 0) ? st0 : st1;
        const float4* tile = (const float4*)(smem + stA * STAGE_T) + (rp << 4);
        const float4* k4   = (const float4*)(smem + st0 * STAGE_T + HALF_B);
        float dot = 0.f, nrm = 0.f, kn = 0.f;
        #pragma unroll
        for (int i = 0; i < 16; ++i) {
            float4 kk = k4[i];
            float4 v  = tile[i ^ rsw];
            dot += v.x * kk.x + v.y * kk.y + v.z * kk.z + v.w * kk.w;
            nrm += v.x * v.x  + v.y * v.y  + v.z * v.z  + v.w * v.w;
            kn  += kk.x * kk.x + kk.y * kk.y + kk.z * kk.z + kk.w * kk.w;
        }
        __syncthreads();         // all threads done reading stages st0, st1

        // ---- Refill freed stages immediately: epilogue runs covered ----
        if (j + 1 < NB) issue_half(st0, bb + 1, 1);   // (2(j+1)+1)%3 == st0
        if (j + 2 < NB) issue_half(st1, bb + 2, 0);   // (2(j+2))%3   == st1

        // ---- Epilogue (3 halves in flight for j < NB-1) ----
        const float beta  = softplus_f(braw);
        const float gg    = 1.f / (1.f + __expf(-graw));
        const float smax  = fmaxf(s0r, fmaxf(s1r, s2r));
        const float e0 = __expf(s0r - smax), e1 = __expf(s1r - smax),
                    e2 = __expf(s2r - smax);
        const float sinv = 1.f / (e0 + e1 + e2);
        const float t0 = e0 * sinv, t1 = e1 * sinv, t2 = e2 * sinv;
        const float gamma = 1.f + softplus_f(gmr);

        const float mem_norm = fmaxf(sqrtf(nrm), 1e-8f);
        const float key_norm = fmaxf(sqrtf(kn), 1e-8f);
        const float z = beta * (dot / (mem_norm * key_norm));

        // softmax without max-subtraction: |z| <= beta (cos in [-1,1]), safe
        const float e = __expf(z);
        float se = warp_sum(e);
        if (lane == 0) redB[wid] = se;
        __syncthreads();
        const float tot = redB[0] + redB[1] + redB[2] + redB[3];
        const float wc = e / tot;

        const float wg = gg * wc + (1.f - gg) * wpv;
        shw[tid] = wg;
        __syncthreads();

        const float wh = shw[(tid + NN - 1) & (NN - 1)] * t0
                       + wg * t1
                       + shw[(tid + 1) & (NN - 1)] * t2;

        const float w = __powf(wh, gamma);
        float sw2 = warp_sum(w);
        if (lane == 0) redA[wid] = sw2;
        __syncthreads();
        const float tw = redA[0] + redA[1] + redA[2] + redA[3] + 1e-16f;

        out[(size_t)bb * NN + tid] = w / tw;
    }
}

extern "C" void kernel_launch(void* const* d_in, const int* in_sizes, int n_in,
                              void* d_out, int out_size) {
    const float* memory  = (const float*)d_in[0];  // [B, N, M]
    const float* k       = (const float*)d_in[1];  // [B, M]
    const float* beta    = (const float*)d_in[2];  // [B, 1]
    const float* g       = (const float*)d_in[3];  // [B, 1]
    const float* s       = (const float*)d_in[4];  // [B, 3]
    const float* gamma   = (const float*)d_in[5];  // [B, 1]
    const float* w_prev  = (const float*)d_in[6];  // [B, N]
    float* out = (float*)d_out;

    static bool attr_set = false;
    if (!attr_set) {
        cudaFuncSetAttribute(rom_kernel,
                             cudaFuncAttributeMaxDynamicSharedMemorySize,
                             SMEM_BYTES);
        attr_set = true;
    }

    int B = in_sizes[0] / (NN * MM);
    rom_kernel<<<B / NB, 128, SMEM_BYTES>>>(memory, k, beta, g, s, gamma,
                                            w_prev, out);
}